// round 8
// baseline (speedup 1.0000x reference)
#include <cuda_runtime.h>
#include <cuda_bf16.h>
#include <cstdint>

#define SS   1024
#define HH   512
#define WW   512
#define BB   32
#define NTHREADS 256
#define CH_PER_THR 2                                  // 32B chunks per thread
#define CH_PER_BLOCK (NTHREADS * CH_PER_THR)          // 512
#define CH_PER_IMG   (HH*WW*3/8)                      // 98304 (8 floats per chunk)
#define BLOCKS_X     (CH_PER_IMG / CH_PER_BLOCK)      // 192

// Per-batch paired stripe LUTs: [b][i]=(row(i),row(i+1)), [b][SS+i]=(col(i),col(i+1))
__device__ float2 g_lut[BB][2 * SS];

// 256-bit global accesses (sm_103): halves instruction count on the global
// streams and is the only width where direct L2 evict qualifiers are legal.
__device__ __forceinline__ void ldg256_evl(const float* p, uint32_t* v) {
    asm("ld.global.nc.L2::evict_last.v8.b32 {%0,%1,%2,%3,%4,%5,%6,%7}, [%8];"
        : "=r"(v[0]), "=r"(v[1]), "=r"(v[2]), "=r"(v[3]),
          "=r"(v[4]), "=r"(v[5]), "=r"(v[6]), "=r"(v[7]) : "l"(p));
}
__device__ __forceinline__ void stg256_evf(float* p, const uint32_t* v) {
    asm volatile("st.global.L2::evict_first.v8.b32 [%0], {%1,%2,%3,%4,%5,%6,%7,%8};"
                 :: "l"(p), "r"(v[0]), "r"(v[1]), "r"(v[2]), "r"(v[3]),
                    "r"(v[4]), "r"(v[5]), "r"(v[6]), "r"(v[7]) : "memory");
}

__device__ __forceinline__ float stripe_val(int i, int st, int lim,
                                            unsigned M, int gb, int length) {
    int d = i - st;
    unsigned u = (unsigned)d;
    unsigned q = (u * M) >> 22;            // exact d/gb for 0<=d<2048
    unsigned rem = u - q * (unsigned)gb;
    return (d >= 0 && d < lim && rem < (unsigned)length) ? 1.0f : 0.0f;
}

__global__ void build_luts(const int* __restrict__ gridblock,
                           const int* __restrict__ start1,
                           const int* __restrict__ start2) {
    const int b   = blockIdx.x;
    const int gb  = gridblock[b];
    const int st1 = start1[b];
    const int st2 = start2[b];
    float lf = __fadd_rn(__fmul_rn((float)gb, 0.6f), 0.5f);
    int length = (int)lf;
    length = min(max(length, 1), gb - 1);
    const int lim = (SS / gb) * gb;
    const unsigned M = (1u << 22) / (unsigned)gb + 1u;
    for (int i = threadIdx.x; i < SS; i += blockDim.x) {
        g_lut[b][i]      = make_float2(stripe_val(i,     st1, lim, M, gb, length),
                                       stripe_val(i + 1, st1, lim, M, gb, length));
        g_lut[b][SS + i] = make_float2(stripe_val(i,     st2, lim, M, gb, length),
                                       stripe_val(i + 1, st2, lim, M, gb, length));
    }
}

__global__ __launch_bounds__(NTHREADS, 6)
void gridmask_kernel(const float* __restrict__ img,
                     const float* __restrict__ angles,
                     float*       __restrict__ out) {
    __shared__ float2 s_lut[2 * SS];     // 16 KB
    __shared__ float  s_trig[2];

    const int b = blockIdx.y;

    // Coalesced LUT fetch from L2-resident scratch (4 float4 / thread)
    {
        const float4* src = reinterpret_cast<const float4*>(g_lut[b]);
        float4* dst = reinterpret_cast<float4*>(s_lut);
        #pragma unroll
        for (int i = 0; i < 4; i++)
            dst[threadIdx.x + i * NTHREADS] = src[threadIdx.x + i * NTHREADS];
    }
    if (threadIdx.x == 0) {
        float a = angles[b];
        s_trig[0] = cosf(a);
        s_trig[1] = sinf(a);
    }
    __syncthreads();

    const float cosv = s_trig[0];
    const float sinv = s_trig[1];
    const float2* rowp = s_lut;
    const float2* colp = s_lut + SS;

    const float* imgb = img + (size_t)b * HH * WW * 3;
    float*       outb = out + (size_t)b * HH * WW * 3;

    // Sampled coords provably within [150,873]: rotation radius
    // sqrt(2)*255.5 = 361.3 < 511.5, so reflection never triggers.
    auto maskpix = [&](unsigned p) -> float {
        float yy = (float)(int)(p >> 9)       - 255.5f;
        float xx = (float)(int)(p & (WW - 1)) - 255.5f;
        float sx = fmaf(cosv, xx, fmaf(sinv,  yy, 511.5f));
        float sy = fmaf(-sinv, xx, fmaf(cosv, yy, 511.5f));
        float x0f = floorf(sx), y0f = floorf(sy);
        float fx = sx - x0f,    fy = sy - y0f;
        float2 rr = rowp[(int)y0f];
        float2 cc = colp[(int)x0f];
        float R = fmaf(fy, rr.y - rr.x, rr.x);
        float C = fmaf(fx, cc.y - cc.x, cc.x);
        return fmaf(C, 1.0f - R, R);      // binary OR: R + C - R*C
    };

    const unsigned c0 = blockIdx.x * CH_PER_BLOCK + threadIdx.x;

    // Phase 1: masks for up to 4 pixels spanned by each 8-float chunk
    float m[CH_PER_THR][4];
    unsigned rr3[CH_PER_THR];
    bool take[CH_PER_THR];
    #pragma unroll
    for (int i = 0; i < CH_PER_THR; i++) {
        unsigned ch = c0 + i * NTHREADS;
        unsigned f0 = ch * 8u;
        unsigned p0 = f0 / 3u;            // compiler magic-mul
        rr3[i] = f0 - p0 * 3u;
        m[i][0] = maskpix(p0);
        m[i][1] = maskpix(p0 + 1);
        m[i][2] = maskpix(p0 + 2);
        m[i][3] = maskpix(p0 + 3);
        take[i] = (fmaxf(fmaxf(m[i][0], m[i][1]), fmaxf(m[i][2], m[i][3])) != 0.0f);
    }

    // Phase 2: predicated back-to-back 256-bit loads (skip exact-zero chunks)
    uint32_t v[CH_PER_THR][8];
    #pragma unroll
    for (int i = 0; i < CH_PER_THR; i++) {
        if (take[i]) {
            ldg256_evl(imgb + (size_t)(c0 + i * NTHREADS) * 8u, v[i]);
        } else {
            #pragma unroll
            for (int j = 0; j < 8; j++) v[i][j] = 0u;
        }
    }

    // Phase 3: multiply + 256-bit stores.
    // Component j belongs to pixel p0 + (r+j)/3.
    #pragma unroll
    for (int i = 0; i < CH_PER_THR; i++) {
        unsigned r = rr3[i];
        uint32_t o[8];
        #pragma unroll
        for (int j = 0; j < 8; j++) {
            unsigned rj = r + (unsigned)j;
            int q = (rj >= 3u) + (rj >= 6u) + (rj >= 9u);
            o[j] = __float_as_uint(__uint_as_float(v[i][j]) * m[i][q]);
        }
        stg256_evf(outb + (size_t)(c0 + i * NTHREADS) * 8u, o);
    }
}

extern "C" void kernel_launch(void* const* d_in, const int* in_sizes, int n_in,
                              void* d_out, int out_size) {
    const float* images    = (const float*)d_in[0];
    const float* angles    = (const float*)d_in[1];
    const int*   gridblock = (const int*)  d_in[2];
    const int*   start1    = (const int*)  d_in[3];
    const int*   start2    = (const int*)  d_in[4];
    float* out = (float*)d_out;

    build_luts<<<BB, 256>>>(gridblock, start1, start2);
    dim3 grid(BLOCKS_X, BB);   // (192, 32)
    gridmask_kernel<<<grid, NTHREADS>>>(images, angles, out);
}

// round 9
// speedup vs baseline: 1.4647x; 1.4647x over previous
#include <cuda_runtime.h>
#include <cuda_fp16.h>
#include <cstdint>

#define SS   1024
#define HH   512
#define WW   512
#define BB   32
#define NTHREADS 256
#define F4_PER_THR 4
#define F4_PER_BLOCK (NTHREADS * F4_PER_THR)         // 1024
#define F4_PER_IMG   (HH*WW*3/4)                     // 196608
#define BLOCKS_X     (F4_PER_IMG / F4_PER_BLOCK)     // 192

// Per-batch paired stripe LUTs in fp16 (values exactly 0.0/1.0 -> lossless):
//   [b][i]      = (rowstripe(i), rowstripe(i+1))
//   [b][SS + i] = (colstripe(i), colstripe(i+1))
__device__ __half2 g_lut[BB][2 * SS];

__device__ __forceinline__ float stripe_val(int i, int st, int lim,
                                            unsigned M, int gb, int length) {
    int d = i - st;
    unsigned u = (unsigned)d;
    unsigned q = (u * M) >> 22;            // exact d/gb for 0<=d<2048
    unsigned rem = u - q * (unsigned)gb;
    return (d >= 0 && d < lim && rem < (unsigned)length) ? 1.0f : 0.0f;
}

__global__ void build_luts(const int* __restrict__ gridblock,
                           const int* __restrict__ start1,
                           const int* __restrict__ start2) {
    const int b   = blockIdx.x;
    const int gb  = gridblock[b];
    const int st1 = start1[b];
    const int st2 = start2[b];
    float lf = __fadd_rn(__fmul_rn((float)gb, 0.6f), 0.5f);
    int length = (int)lf;
    length = min(max(length, 1), gb - 1);
    const int lim = (SS / gb) * gb;
    const unsigned M = (1u << 22) / (unsigned)gb + 1u;
    for (int i = threadIdx.x; i < SS; i += blockDim.x) {
        g_lut[b][i]      = __floats2half2_rn(stripe_val(i,     st1, lim, M, gb, length),
                                             stripe_val(i + 1, st1, lim, M, gb, length));
        g_lut[b][SS + i] = __floats2half2_rn(stripe_val(i,     st2, lim, M, gb, length),
                                             stripe_val(i + 1, st2, lim, M, gb, length));
    }
}

__global__ __launch_bounds__(NTHREADS, 8)
void gridmask_kernel(const float* __restrict__ img,
                     const float* __restrict__ angles,
                     float*       __restrict__ out) {
    __shared__ __half2 s_lut[2 * SS];    // 8 KB
    __shared__ float   s_trig[2];

    const int b = blockIdx.y;

    // Coalesced LUT fetch from L2-resident scratch (2 float4 / thread)
    {
        const float4* src = reinterpret_cast<const float4*>(g_lut[b]);
        float4* dst = reinterpret_cast<float4*>(s_lut);
        #pragma unroll
        for (int i = 0; i < 2; i++)
            dst[threadIdx.x + i * NTHREADS] = src[threadIdx.x + i * NTHREADS];
    }
    if (threadIdx.x == 0) {
        float a = angles[b];
        s_trig[0] = cosf(a);
        s_trig[1] = sinf(a);
    }
    __syncthreads();

    const float cosv = s_trig[0];
    const float sinv = s_trig[1];
    const __half2* rowp = s_lut;
    const __half2* colp = s_lut + SS;

    const float4* imgb4 = reinterpret_cast<const float4*>(img + (size_t)b * HH * WW * 3);
    float4*       outb4 = reinterpret_cast<float4*>(out + (size_t)b * HH * WW * 3);

    const unsigned a0 = blockIdx.x * F4_PER_BLOCK + threadIdx.x;

    // Phase 1: front-batched independent streaming loads (max MLP)
    float4 v[F4_PER_THR];
    #pragma unroll
    for (int i = 0; i < F4_PER_THR; i++)
        v[i] = __ldcs(&imgb4[a0 + i * NTHREADS]);

    // Phase 2: masks for the two pixels each float4 spans (hides load latency).
    // Sampled coords provably within [150,873]: rotation radius
    // sqrt(2)*255.5 = 361.3 < 511.5, so reflection never triggers.
    auto maskpix = [&](unsigned p) -> float {
        float yy = (float)(int)(p >> 9)       - 255.5f;
        float xx = (float)(int)(p & (WW - 1)) - 255.5f;
        float sx = fmaf(cosv, xx, fmaf(sinv,  yy, 511.5f));
        float sy = fmaf(-sinv, xx, fmaf(cosv, yy, 511.5f));
        float x0f = floorf(sx), y0f = floorf(sy);
        float fx = sx - x0f,    fy = sy - y0f;
        float2 rr = __half22float2(rowp[(int)y0f]);
        float2 cc = __half22float2(colp[(int)x0f]);
        float R = fmaf(fy, rr.y - rr.x, rr.x);
        float C = fmaf(fx, cc.y - cc.x, cc.x);
        return fmaf(C, 1.0f - R, R);      // binary OR: R + C - R*C
    };

    float mA[F4_PER_THR], mB[F4_PER_THR];
    int   r3[F4_PER_THR];
    #pragma unroll
    for (int i = 0; i < F4_PER_THR; i++) {
        unsigned f0 = (a0 + i * NTHREADS) * 4u;
        unsigned p  = f0 / 3u;            // compiler magic-mul
        r3[i] = (int)(f0 - p * 3u);
        mA[i] = maskpix(p);
        mB[i] = maskpix(p + 1);
    }

    // Phase 3: multiply + coalesced streaming stores
    // component->pixel by f0 mod 3:
    //   r=0: x,y,z->A w->B ; r=1: x,y->A z,w->B ; r=2: x->A y,z,w->B
    #pragma unroll
    for (int i = 0; i < F4_PER_THR; i++) {
        float my = (r3[i] == 2) ? mB[i] : mA[i];
        float mz = (r3[i] == 0) ? mA[i] : mB[i];
        float4 o = make_float4(v[i].x * mA[i], v[i].y * my,
                               v[i].z * mz,    v[i].w * mB[i]);
        __stcs(&outb4[a0 + i * NTHREADS], o);
    }
}

extern "C" void kernel_launch(void* const* d_in, const int* in_sizes, int n_in,
                              void* d_out, int out_size) {
    const float* images    = (const float*)d_in[0];
    const float* angles    = (const float*)d_in[1];
    const int*   gridblock = (const int*)  d_in[2];
    const int*   start1    = (const int*)  d_in[3];
    const int*   start2    = (const int*)  d_in[4];
    float* out = (float*)d_out;

    build_luts<<<BB, 256>>>(gridblock, start1, start2);
    dim3 grid(BLOCKS_X, BB);   // (192, 32)
    gridmask_kernel<<<grid, NTHREADS>>>(images, angles, out);
}

// round 10
// speedup vs baseline: 1.4952x; 1.0209x over previous
#include <cuda_runtime.h>
#include <cuda_fp16.h>
#include <cstdint>

#define SS   1024
#define HH   512
#define WW   512
#define BB   32
#define NTHREADS 256
#define F4_PER_THR 4
#define F4_PER_BLOCK (NTHREADS * F4_PER_THR)         // 1024
#define F4_PER_IMG   (HH*WW*3/4)                     // 196608
#define BLOCKS_X     (F4_PER_IMG / F4_PER_BLOCK)     // 192

__device__ __forceinline__ float stripe_val(int i, int st, int lim,
                                            unsigned M, int gb, int length) {
    int d = i - st;
    unsigned u = (unsigned)d;
    unsigned q = (u * M) >> 22;            // exact d/gb for 0<=d<2048
    unsigned rem = u - q * (unsigned)gb;
    return (d >= 0 && d < lim && rem < (unsigned)length) ? 1.0f : 0.0f;
}

__global__ __launch_bounds__(NTHREADS, 8)
void gridmask_kernel(const float* __restrict__ img,
                     const float* __restrict__ angles,
                     const int*   __restrict__ gridblock,
                     const int*   __restrict__ start1,
                     const int*   __restrict__ start2,
                     float*       __restrict__ out) {
    // fp16 paired stripe LUTs (values exactly 0.0/1.0 -> lossless):
    //   s_lut[i]      = (rowstripe(i), rowstripe(i+1))
    //   s_lut[SS + i] = (colstripe(i), colstripe(i+1))
    __shared__ __half2 s_lut[2 * SS];    // 8 KB
    __shared__ float   s_trig[2];

    const int b = blockIdx.y;

    // In-block LUT build (fused; ~160 instr/thread, <0.5% of block work)
    {
        const int gb  = gridblock[b];
        const int st1 = start1[b];
        const int st2 = start2[b];
        float lf = __fadd_rn(__fmul_rn((float)gb, 0.6f), 0.5f);
        int length = (int)lf;
        length = min(max(length, 1), gb - 1);
        const int lim = (SS / gb) * gb;
        const unsigned M = (1u << 22) / (unsigned)gb + 1u;
        #pragma unroll
        for (int i = threadIdx.x; i < SS; i += NTHREADS) {
            s_lut[i]      = __floats2half2_rn(stripe_val(i,     st1, lim, M, gb, length),
                                              stripe_val(i + 1, st1, lim, M, gb, length));
            s_lut[SS + i] = __floats2half2_rn(stripe_val(i,     st2, lim, M, gb, length),
                                              stripe_val(i + 1, st2, lim, M, gb, length));
        }
    }
    if (threadIdx.x == 0) {
        float a = angles[b];
        s_trig[0] = cosf(a);
        s_trig[1] = sinf(a);
    }
    __syncthreads();

    const float cosv = s_trig[0];
    const float sinv = s_trig[1];
    const __half2* rowp = s_lut;
    const __half2* colp = s_lut + SS;

    const float4* imgb4 = reinterpret_cast<const float4*>(img + (size_t)b * HH * WW * 3);
    float4*       outb4 = reinterpret_cast<float4*>(out + (size_t)b * HH * WW * 3);

    const unsigned a0 = blockIdx.x * F4_PER_BLOCK + threadIdx.x;

    // Phase 1: front-batched independent streaming loads (max MLP)
    float4 v[F4_PER_THR];
    #pragma unroll
    for (int i = 0; i < F4_PER_THR; i++)
        v[i] = __ldcs(&imgb4[a0 + i * NTHREADS]);

    // Phase 2: masks for the two pixels each float4 spans (hides load latency).
    // Sampled coords provably within [150,873]: rotation radius
    // sqrt(2)*255.5 = 361.3 < 511.5, so reflection never triggers.
    auto maskpix = [&](unsigned p) -> float {
        float yy = (float)(int)(p >> 9)       - 255.5f;
        float xx = (float)(int)(p & (WW - 1)) - 255.5f;
        float sx = fmaf(cosv, xx, fmaf(sinv,  yy, 511.5f));
        float sy = fmaf(-sinv, xx, fmaf(cosv, yy, 511.5f));
        float x0f = floorf(sx), y0f = floorf(sy);
        float fx = sx - x0f,    fy = sy - y0f;
        float2 rr = __half22float2(rowp[(int)y0f]);
        float2 cc = __half22float2(colp[(int)x0f]);
        float R = fmaf(fy, rr.y - rr.x, rr.x);
        float C = fmaf(fx, cc.y - cc.x, cc.x);
        return fmaf(C, 1.0f - R, R);      // binary OR: R + C - R*C
    };

    float mA[F4_PER_THR], mB[F4_PER_THR];
    int   r3[F4_PER_THR];
    #pragma unroll
    for (int i = 0; i < F4_PER_THR; i++) {
        unsigned f0 = (a0 + i * NTHREADS) * 4u;
        unsigned p  = f0 / 3u;            // compiler magic-mul
        r3[i] = (int)(f0 - p * 3u);
        mA[i] = maskpix(p);
        mB[i] = maskpix(p + 1);
    }

    // Phase 3: multiply + coalesced streaming stores
    // component->pixel by f0 mod 3:
    //   r=0: x,y,z->A w->B ; r=1: x,y->A z,w->B ; r=2: x->A y,z,w->B
    #pragma unroll
    for (int i = 0; i < F4_PER_THR; i++) {
        float my = (r3[i] == 2) ? mB[i] : mA[i];
        float mz = (r3[i] == 0) ? mA[i] : mB[i];
        float4 o = make_float4(v[i].x * mA[i], v[i].y * my,
                               v[i].z * mz,    v[i].w * mB[i]);
        __stcs(&outb4[a0 + i * NTHREADS], o);
    }
}

extern "C" void kernel_launch(void* const* d_in, const int* in_sizes, int n_in,
                              void* d_out, int out_size) {
    const float* images    = (const float*)d_in[0];
    const float* angles    = (const float*)d_in[1];
    const int*   gridblock = (const int*)  d_in[2];
    const int*   start1    = (const int*)  d_in[3];
    const int*   start2    = (const int*)  d_in[4];
    float* out = (float*)d_out;

    dim3 grid(BLOCKS_X, BB);   // (192, 32)
    gridmask_kernel<<<grid, NTHREADS>>>(images, angles, gridblock, start1, start2, out);
}